// round 16
// baseline (speedup 1.0000x reference)
#include <cuda_runtime.h>
#include <cstdint>

// x: [2][4][8][8][8][96][96] f32, W: [9][4][4][3][3][3] f32, b: [9][4] f32
// out: [2][4][6][6][8][96][96] f32
#define HW_PLANE 9216
#define SLOTF    480                 // floats per slot: 5 rows x 96, unpadded (gmem layout)
typedef unsigned long long u64;

// Winograd-transformed weights: [n(108)][kh(3)][comp(5)] x ulonglong2{(o0,o1),(o2,o3)}
__constant__ ulonglong2 c_w2[1620];
__device__   ulonglong2 g_w2[1620];

__device__ __forceinline__ u64 pack2(float lo, float hi) {
    u64 r; asm("mov.b64 %0, {%1, %2};" : "=l"(r) : "f"(lo), "f"(hi)); return r;
}
__device__ __forceinline__ void ffma2(u64& a, u64 x, u64 w) {
    asm("fma.rn.f32x2 %0, %1, %2, %0;" : "+l"(a) : "l"(x), "l"(w));
}
__device__ __forceinline__ float2 unpack2(u64 v) {
    float lo, hi; asm("mov.b64 {%0, %1}, %2;" : "=f"(lo), "=f"(hi) : "l"(v));
    return make_float2(lo, hi);
}
__device__ __forceinline__ void mbar_init(uint32_t mbar) {
    asm volatile("mbarrier.init.shared.b64 [%0], 1;" :: "r"(mbar) : "memory");
}
__device__ __forceinline__ void mbar_expect(uint32_t mbar, uint32_t bytes) {
    asm volatile("mbarrier.arrive.expect_tx.shared.b64 _, [%0], %1;"
                 :: "r"(mbar), "r"(bytes) : "memory");
}
__device__ __forceinline__ void mbar_wait(uint32_t mbar, uint32_t parity) {
    asm volatile(
        "{\n\t.reg .pred P;\n\t"
        "WL_%=:\n\t"
        "mbarrier.try_wait.parity.acquire.cta.shared::cta.b64 P, [%0], %1, 0x989680;\n\t"
        "@!P bra WL_%=;\n\t"
        "}" :: "r"(mbar), "r"(parity) : "memory");
}
__device__ __forceinline__ void bulk_g2s(uint32_t dst, const void* src, uint32_t bytes, uint32_t mbar) {
    asm volatile("cp.async.bulk.shared::cta.global.mbarrier::complete_tx::bytes [%0], [%1], %2, [%3];"
                 :: "r"(dst), "l"(src), "r"(bytes), "r"(mbar) : "memory");
}
__device__ __forceinline__ void fence_proxy_async_cta() {
    asm volatile("fence.proxy.async.shared::cta;" ::: "memory");
}

// ---- prep: Winograd weight transform into g_w2 (then host memcpys to c_w2)
__global__ void wprep_kernel(const float* __restrict__ Wg) {
    float* gw = reinterpret_cast<float*>(g_w2);
    for (int u = threadIdx.x; u < 1296; u += blockDim.x) {
        int o  = u & 3;
        int kh = (u >> 2) % 3;
        int nn = u / 12;             // (ci*9+ij)*3+kd
        int kd = nn % 3;
        int ij = (nn / 3) % 9;
        int ci = nn / 27;
        const float* wp = Wg + ((ij * 4 + o) * 4 + ci) * 27 + kd * 9 + kh * 3;
        float g0 = wp[0], g1 = wp[1], g2 = wp[2];
        float* dst = gw + (nn * 3 + kh) * 20 + o;    // comp stride 4 floats
        dst[0]  = 0.5f * g0;
        dst[4]  = 0.5f * (g0 + g1 + g2);
        dst[8]  = (g0 - g1 + g2) * (1.f / 6.f);
        dst[12] = (g0 + 2.f * g1 + 4.f * g2) * (1.f / 6.f);
        dst[16] = g2;
    }
}

// Winograd F(3,3) along w. Block: 256 thr = 8 warps; warp = 3 out rows x 96 (lane: 3 cols),
// 4 o-chans. 108 iters = 36 macro (ci,i,j) x kd(0..2), slot = kd. Per-warp 5-row slots via
// one cp.async.bulk + per-warp mbarrier. Weights in __constant__ (LDCU/uniform path — off
// L1 and hopefully out of the FFMA2 RF-bank equation). 2 blocks/SM.
__global__ __launch_bounds__(256, 2)
void conv5d_kernel(const float* __restrict__ x,
                   const float* __restrict__ bg,
                   float* __restrict__ out)
{
    extern __shared__ __align__(16) float tiles[];     // [8 warps][3 slots][SLOTF] + 4 pad
    __shared__ __align__(8) u64 mbars[8][3];
    __shared__ float mbsh[4];

    const int tid   = threadIdx.x;
    const int warp  = tid >> 5;
    const int lane  = tid & 31;
    const int htile = blockIdx.x % 4;
    const int d     = blockIdx.x / 4;
    const int t     = blockIdx.y;
    const int c     = blockIdx.z % 6;
    const int b     = blockIdx.z / 6;
    const int h0    = htile * 24;

    if (tid < 4) {
        float s = 0.f;
        #pragma unroll
        for (int ij = 0; ij < 9; ij++) s += bg[ij * 4 + tid];
        mbsh[tid] = s * (1.0f / 9.0f);
    }

    float* slab = tiles + warp * (3 * SLOTF);
    const bool v0 = (d >= 1), v2 = (d <= 6);

    // ---- per-warp bulk-copy geometry: 5 gmem-contiguous rows h0+3w-1 .. h0+3w+3
    const int hstart = h0 + 3 * warp - 1;
    const int cstart = (hstart < 0) ? 0 : hstart;
    const int cend   = (hstart + 5 > 96) ? 96 : (hstart + 5);
    const uint32_t cbytes  = (uint32_t)(cend - cstart) * 384u;   // 1920 or 1536
    const uint32_t dstoffB = (uint32_t)(cstart - hstart) * 384u; // 0 or 384
    const int      srcfo   = cstart * 96;

    // ---- static zeroing: invalid h rows, invalid kd slots
    if (hstart < 0) {            // h=-1 row (row0) of every slot
        #pragma unroll
        for (int s = 0; s < 3; s++) {
            #pragma unroll
            for (int k = 0; k < 3; k++) slab[s * SLOTF + lane * 3 + k] = 0.f;
        }
    }
    if (hstart + 5 > 96) {       // h=96 row (row4) of every slot
        #pragma unroll
        for (int s = 0; s < 3; s++) {
            #pragma unroll
            for (int k = 0; k < 3; k++) slab[s * SLOTF + 384 + lane * 3 + k] = 0.f;
        }
    }
    if (!v0) {                   // d=0: slot0 stays zero
        #pragma unroll
        for (int k = 0; k < 15; k++) slab[lane + 32 * k] = 0.f;
    }
    if (!v2) {                   // d=7: slot2 stays zero
        #pragma unroll
        for (int k = 0; k < 15; k++) slab[2 * SLOTF + lane + 32 * k] = 0.f;
    }

    const uint32_t sb  = (uint32_t)__cvta_generic_to_shared(slab);
    const uint32_t mb0 = (uint32_t)__cvta_generic_to_shared(&mbars[warp][0]);
    const uint32_t mb1 = mb0 + 8, mb2 = mb0 + 16;
    if (lane == 0) { mbar_init(mb0); mbar_init(mb1); mbar_init(mb2); }
    fence_proxy_async_cta();
    __syncthreads();             // mbsh/zeroing/mbar init visible; only block barrier

    auto issue = [&](int s, uint32_t mb, const float* plane) {
        if (lane == 0) {
            mbar_expect(mb, cbytes);
            bulk_g2s(sb + (uint32_t)s * (SLOTF * 4) + dstoffB, plane + srcfo, cbytes, mb);
        }
    };

    // Winograd-domain accumulators: 3 output rows x 5 comps x 2 o-pairs
    u64 a01[3][5], a23[3][5];
    #pragma unroll
    for (int py = 0; py < 3; py++) {
        #pragma unroll
        for (int cm = 0; cm < 5; cm++) { a01[py][cm] = 0ull; a23[py][cm] = 0ull; }
    }

    const int  lzoff = (lane == 0) ? 0 : -1;
    const bool lz    = (lane == 0);
    const bool rz    = (lane == 31);

    auto transform_row = [&](const float* rw, u64* T) {
        float am = rw[lzoff];
        float d0 = lz ? 0.f : am;
        float d1 = rw[0], d2 = rw[1], d3 = rw[2];
        float a4 = rw[3];
        float d4 = rz ? 0.f : a4;
        float t3 = d3 - d1;
        float t1 = fmaf(2.f, d1, d2 - d3);
        float t2 = fmaf(3.f, d2, -fmaf(2.f, d1, d3));
        float t0 = fmaf(2.f, d0 - d2, t3);
        float t4 = fmaf(-2.f, t3, d4 - d2);
        T[0] = pack2(t0, t0); T[1] = pack2(t1, t1); T[2] = pack2(t2, t2);
        T[3] = pack2(t3, t3); T[4] = pack2(t4, t4);
    };
    // one kh tap-row to 3 output rows; weights from __constant__ (uniform index)
    auto fmakh3 = [&](const u64* P0, const u64* P1, const u64* P2, int wbase) {
        #pragma unroll
        for (int cm = 0; cm < 5; cm++) {
            ulonglong2 w2 = c_w2[wbase + cm];
            ffma2(a01[0][cm], P0[cm], w2.x); ffma2(a23[0][cm], P0[cm], w2.y);
            ffma2(a01[1][cm], P1[cm], w2.x); ffma2(a23[1][cm], P1[cm], w2.y);
            ffma2(a01[2][cm], P2[cm], w2.x); ffma2(a23[2][cm], P2[cm], w2.y);
        }
    };
    auto compute = [&](int n, const float* slot) {
        const int wbase = n * 15;
        const float* tb = slot + 3 * lane;
        u64 R0[5], R1[5], R2[5];
        transform_row(tb,        R0);
        transform_row(tb + 96,   R1);
        transform_row(tb + 192,  R2);
        fmakh3(R0, R1, R2, wbase);           // kh = 0 (rows 0,1,2)
        transform_row(tb + 288,  R0);        // row 3
        fmakh3(R1, R2, R0, wbase + 5);       // kh = 1 (rows 1,2,3)
        transform_row(tb + 384,  R1);        // row 4
        fmakh3(R2, R0, R1, wbase + 10);      // kh = 2 (rows 2,3,4)
    };

    const float* bm = x + (size_t)b * (4 * 8 * 8 * 8 * HW_PLANE)
                    + ((size_t)((c * 8 + t) * 8) + (d - 1)) * HW_PLANE;  // dz = d-1 plane

    if (v0) issue(0, mb0, bm);
    issue(1, mb1, bm + HW_PLANE);

    uint32_t p0 = 0, p1 = 0, p2 = 0;
    int n = 0;

    #pragma unroll 1
    for (int ci = 0; ci < 4; ci++) {
        #pragma unroll 1
        for (int i = 0; i < 3; i++) {
            #pragma unroll
            for (int j = 0; j < 3; j++) {
                const bool last = (ci == 3) && (i == 2) && (j == 2);
                const float* bn = bm + (size_t)((j < 2) ? 8 : ((i < 2) ? 48 : 368)) * HW_PLANE;

                // kd = 0
                if (v0) { mbar_wait(mb0, p0); p0 ^= 1u; }
                if (v2) issue(2, mb2, bm + 2 * HW_PLANE);
                compute(n, slab);

                // kd = 1
                mbar_wait(mb1, p1); p1 ^= 1u;
                if (!last && v0) issue(0, mb0, bn);
                compute(n + 1, slab + SLOTF);

                // kd = 2
                if (v2) { mbar_wait(mb2, p2); p2 ^= 1u; }
                if (!last) issue(1, mb1, bn + HW_PLANE);
                compute(n + 2, slab + 2 * SLOTF);

                n += 3;
                bm = bn;
            }
        }
    }

    // ---- epilogue: inverse Winograd + scale + bias
    const float invn = 1.0f / 9.0f;
    const float mb[4] = { mbsh[0], mbsh[1], mbsh[2], mbsh[3] };
    size_t ob = ((((size_t)(b * 4) * 6 + c) * 6 + t) * 8 + d) * (size_t)HW_PLANE;
    const size_t ostride = (size_t)6 * 6 * 8 * HW_PLANE;

    #pragma unroll
    for (int py = 0; py < 3; py++) {
        int h = h0 + 3 * warp + py;
        size_t rowoff = ob + (size_t)h * 96 + 3 * lane;
        float M[4][5];
        #pragma unroll
        for (int cm = 0; cm < 5; cm++) {
            float2 A = unpack2(a01[py][cm]);
            float2 B = unpack2(a23[py][cm]);
            M[0][cm] = A.x; M[1][cm] = A.y; M[2][cm] = B.x; M[3][cm] = B.y;
        }
        #pragma unroll
        for (int o = 0; o < 4; o++) {
            float y0 = M[o][0] + M[o][1] + M[o][2] + M[o][3];
            float y1 = M[o][1] - M[o][2] + 2.f * M[o][3];
            float y2 = M[o][1] + M[o][2] + fmaf(4.f, M[o][3], M[o][4]);
            float* op = out + rowoff + (size_t)o * ostride;
            op[0] = fmaf(y0, invn, mb[o]);
            op[1] = fmaf(y1, invn, mb[o]);
            op[2] = fmaf(y2, invn, mb[o]);
        }
    }
}

extern "C" void kernel_launch(void* const* d_in, const int* in_sizes, int n_in,
                              void* d_out, int out_size) {
    const float* x  = (const float*)d_in[0];
    const float* Wg = (const float*)d_in[1];
    const float* bg = (const float*)d_in[2];
    float* out = (float*)d_out;

    // 1) transform weights into g_w2 (device global)
    wprep_kernel<<<1, 256>>>(Wg);
    // 2) stage into constant bank (device-to-device async copy; graph-capturable)
    void* gptr = nullptr;
    cudaGetSymbolAddress(&gptr, g_w2);
    cudaMemcpyToSymbolAsync(c_w2, gptr, sizeof(ulonglong2) * 1620, 0,
                            cudaMemcpyDeviceToDevice, 0);

    const int dynsmem = (8 * 3 * SLOTF + 4) * (int)sizeof(float);   // 46096 B
    cudaFuncSetAttribute(conv5d_kernel, cudaFuncAttributeMaxDynamicSharedMemorySize, dynsmem);

    dim3 grid(32, 6, 12);   // x: htile(4) + 4*d(8); y: t(6); z: b*6+c(12)
    dim3 block(256);
    conv5d_kernel<<<grid, block, dynsmem>>>(x, bg, out);
}

// round 17
// speedup vs baseline: 1.1487x; 1.1487x over previous
#include <cuda_runtime.h>
#include <cstdint>

// x: [2][4][8][8][8][96][96] f32, W: [9][4][4][3][3][3] f32, b: [9][4] f32
// out: [2][4][6][6][8][96][96] f32
#define HW_PLANE 9216
#define YPLANE   15360               // transformed plane: 96 rows x (5 comps x 32 lanes)
#define SLOTF    800                 // floats per slot: 5 y-rows x 160
typedef unsigned long long u64;

// pass-1 scratch: w-transformed x, y[plane(4096)][h(96)][comp(5)][lane(32)]
__device__ float g_y[4096ull * YPLANE];

__device__ __forceinline__ u64 pack2(float lo, float hi) {
    u64 r; asm("mov.b64 %0, {%1, %2};" : "=l"(r) : "f"(lo), "f"(hi)); return r;
}
__device__ __forceinline__ void ffma2(u64& a, u64 x, u64 w) {
    asm("fma.rn.f32x2 %0, %1, %2, %0;" : "+l"(a) : "l"(x), "l"(w));
}
__device__ __forceinline__ float2 unpack2(u64 v) {
    float lo, hi; asm("mov.b64 {%0, %1}, %2;" : "=f"(lo), "=f"(hi) : "l"(v));
    return make_float2(lo, hi);
}
__device__ __forceinline__ void mbar_init(uint32_t mbar) {
    asm volatile("mbarrier.init.shared.b64 [%0], 1;" :: "r"(mbar) : "memory");
}
__device__ __forceinline__ void mbar_expect(uint32_t mbar, uint32_t bytes) {
    asm volatile("mbarrier.arrive.expect_tx.shared.b64 _, [%0], %1;"
                 :: "r"(mbar), "r"(bytes) : "memory");
}
__device__ __forceinline__ void mbar_wait(uint32_t mbar, uint32_t parity) {
    asm volatile(
        "{\n\t.reg .pred P;\n\t"
        "WL_%=:\n\t"
        "mbarrier.try_wait.parity.acquire.cta.shared::cta.b64 P, [%0], %1, 0x989680;\n\t"
        "@!P bra WL_%=;\n\t"
        "}" :: "r"(mbar), "r"(parity) : "memory");
}
__device__ __forceinline__ void bulk_g2s(uint32_t dst, const void* src, uint32_t bytes, uint32_t mbar) {
    asm volatile("cp.async.bulk.shared::cta.global.mbarrier::complete_tx::bytes [%0], [%1], %2, [%3];"
                 :: "r"(dst), "l"(src), "r"(bytes), "r"(mbar) : "memory");
}
__device__ __forceinline__ void fence_proxy_async_cta() {
    asm volatile("fence.proxy.async.shared::cta;" ::: "memory");
}

// ---- pass 1: Winograd F(3,3) data transform along w, per plane row.
// T0=2d0-d1-2d2+d3, T1=2d1+d2-d3, T2=-2d1+3d2-d3, T3=d3-d1, T4=2d1-d2-2d3+d4
__global__ __launch_bounds__(256)
void xform_kernel(const float* __restrict__ x) {
    const int plane = blockIdx.x;
    const float* xp = x + (size_t)plane * HW_PLANE;
    float* yp = g_y + (size_t)plane * YPLANE;
    for (int u = threadIdx.x; u < 3072; u += 256) {
        int row = u >> 5, l = u & 31;
        const float* rw = xp + row * 96 + 3 * l;
        float d0 = (l == 0)  ? 0.f : rw[-1];
        float d1 = rw[0], d2 = rw[1], d3 = rw[2];
        float d4 = (l == 31) ? 0.f : rw[3];
        float t3 = d3 - d1;
        float* yo = yp + row * 160 + l;
        yo[0]   = fmaf(2.f, d0 - d2, t3);
        yo[32]  = fmaf(2.f, d1, d2 - d3);
        yo[64]  = fmaf(3.f, d2, -fmaf(2.f, d1, d3));
        yo[96]  = t3;
        yo[128] = fmaf(-2.f, t3, d4 - d2);
    }
}

// ---- pass 2: R12 structure on pre-transformed data. Block: 256 thr = 8 warps;
// warp = 3 out rows x 96 (lane: 3 cols), 4 o-chans. 108 iters = 36 macro x kd, slot = kd.
// Per-warp 5-row y-slots via one cp.async.bulk + per-warp mbarrier. 2 blocks/SM.
__global__ __launch_bounds__(256, 2)
void conv5d_kernel(const float* __restrict__ Wg,
                   const float* __restrict__ bg,
                   float* __restrict__ out)
{
    extern __shared__ __align__(16) float tiles[];     // [8 warps][3 slots][SLOTF] + 4 pad
    __shared__ __align__(16) float wsh[6480];          // [n(108)][kh(3)][comp(5)][o(4)]
    __shared__ __align__(8) u64 mbars[8][3];
    __shared__ float mbsh[4];

    const int tid   = threadIdx.x;
    const int warp  = tid >> 5;
    const int lane  = tid & 31;
    const int htile = blockIdx.x % 4;
    const int d     = blockIdx.x / 4;
    const int t     = blockIdx.y;
    const int c     = blockIdx.z % 6;
    const int b     = blockIdx.z / 6;
    const int h0    = htile * 24;

    // ---- stage Winograd-transformed weights (G): wsh[(n*3+kh)*20 + comp*4 + o]
    for (int u = tid; u < 1296; u += 256) {
        int o  = u & 3;
        int kh = (u >> 2) % 3;
        int nn = u / 12;
        int kd = nn % 3;
        int ij = (nn / 3) % 9;
        int ci = nn / 27;
        const float* wp = Wg + ((ij * 4 + o) * 4 + ci) * 27 + kd * 9 + kh * 3;
        float g0 = wp[0], g1 = wp[1], g2 = wp[2];
        float* dst = wsh + (nn * 3 + kh) * 20 + o;
        dst[0]  = 0.5f * g0;
        dst[4]  = 0.5f * (g0 + g1 + g2);
        dst[8]  = (g0 - g1 + g2) * (1.f / 6.f);
        dst[12] = (g0 + 2.f * g1 + 4.f * g2) * (1.f / 6.f);
        dst[16] = g2;
    }
    if (tid < 4) {
        float s = 0.f;
        #pragma unroll
        for (int ij = 0; ij < 9; ij++) s += bg[ij * 4 + tid];
        mbsh[tid] = s * (1.0f / 9.0f);
    }

    float* slab = tiles + warp * (3 * SLOTF);
    const bool v0 = (d >= 1), v2 = (d <= 6);

    // ---- per-warp bulk-copy geometry: 5 y-rows h0+3w-1 .. h0+3w+3 (640 B each, contiguous)
    const int hstart = h0 + 3 * warp - 1;
    const int cstart = (hstart < 0) ? 0 : hstart;
    const int cend   = (hstart + 5 > 96) ? 96 : (hstart + 5);
    const uint32_t cbytes  = (uint32_t)(cend - cstart) * 640u;   // 3200 or 2560
    const uint32_t dstoffB = (uint32_t)(cstart - hstart) * 640u; // 0 or 640
    const int      srcfo   = cstart * 160;

    // ---- static zeroing: invalid h rows (160 floats each), invalid kd slots
    if (hstart < 0) {            // h=-1 row (row0) of every slot
        #pragma unroll
        for (int s = 0; s < 3; s++) {
            #pragma unroll
            for (int k = 0; k < 5; k++) slab[s * SLOTF + k * 32 + lane] = 0.f;
        }
    }
    if (hstart + 5 > 96) {       // h=96 row (row4) of every slot
        #pragma unroll
        for (int s = 0; s < 3; s++) {
            #pragma unroll
            for (int k = 0; k < 5; k++) slab[s * SLOTF + 640 + k * 32 + lane] = 0.f;
        }
    }
    if (!v0) {                   // d=0: slot0 stays zero
        #pragma unroll
        for (int k = 0; k < 25; k++) slab[lane + 32 * k] = 0.f;
    }
    if (!v2) {                   // d=7: slot2 stays zero
        #pragma unroll
        for (int k = 0; k < 25; k++) slab[2 * SLOTF + lane + 32 * k] = 0.f;
    }

    const uint32_t sb  = (uint32_t)__cvta_generic_to_shared(slab);
    const uint32_t mb0 = (uint32_t)__cvta_generic_to_shared(&mbars[warp][0]);
    const uint32_t mb1 = mb0 + 8, mb2 = mb0 + 16;
    if (lane == 0) { mbar_init(mb0); mbar_init(mb1); mbar_init(mb2); }
    fence_proxy_async_cta();
    __syncthreads();             // wsh/mbsh/zeroing/mbar init visible; only block barrier

    auto issue = [&](int s, uint32_t mb, const float* plane) {
        if (lane == 0) {
            mbar_expect(mb, cbytes);
            bulk_g2s(sb + (uint32_t)s * (SLOTF * 4) + dstoffB, plane + srcfo, cbytes, mb);
        }
    };

    // Winograd-domain accumulators: 3 output rows x 5 comps x 2 o-pairs
    u64 a01[3][5], a23[3][5];
    #pragma unroll
    for (int py = 0; py < 3; py++) {
        #pragma unroll
        for (int cm = 0; cm < 5; cm++) { a01[py][cm] = 0ull; a23[py][cm] = 0ull; }
    }

    // load one pre-transformed row: 5 LDS.32 (conflict-free) + 5 dup-packs
    auto loadrow = [&](const float* rw, u64* T) {
        #pragma unroll
        for (int cm = 0; cm < 5; cm++) { float v = rw[cm * 32]; T[cm] = pack2(v, v); }
    };
    auto fmakh3 = [&](const u64* P0, const u64* P1, const u64* P2, const ulonglong2* wb) {
        #pragma unroll
        for (int cm = 0; cm < 5; cm++) {
            ulonglong2 w2 = wb[cm];
            ffma2(a01[0][cm], P0[cm], w2.x); ffma2(a23[0][cm], P0[cm], w2.y);
            ffma2(a01[1][cm], P1[cm], w2.x); ffma2(a23[1][cm], P1[cm], w2.y);
            ffma2(a01[2][cm], P2[cm], w2.x); ffma2(a23[2][cm], P2[cm], w2.y);
        }
    };
    const ulonglong2* W2 = reinterpret_cast<const ulonglong2*>(wsh);
    auto compute = [&](int n, const float* slot) {
        const ulonglong2* wb = W2 + n * 15;
        const float* tb = slot + lane;
        u64 R0[5], R1[5], R2[5];
        loadrow(tb,        R0);
        loadrow(tb + 160,  R1);
        loadrow(tb + 320,  R2);
        fmakh3(R0, R1, R2, wb);          // kh = 0 (rows 0,1,2)
        loadrow(tb + 480,  R0);          // row 3
        fmakh3(R1, R2, R0, wb + 5);      // kh = 1 (rows 1,2,3)
        loadrow(tb + 640,  R1);          // row 4
        fmakh3(R2, R0, R1, wb + 10);     // kh = 2 (rows 2,3,4)
    };

    const float* bm = g_y + ((size_t)b * 2048 + (size_t)((c * 8 + t) * 8) + (d - 1)) * YPLANE;

    if (v0) issue(0, mb0, bm);
    issue(1, mb1, bm + YPLANE);

    uint32_t p0 = 0, p1 = 0, p2 = 0;
    int n = 0;

    #pragma unroll 1
    for (int ci = 0; ci < 4; ci++) {
        #pragma unroll 1
        for (int i = 0; i < 3; i++) {
            #pragma unroll
            for (int j = 0; j < 3; j++) {
                const bool last = (ci == 3) && (i == 2) && (j == 2);
                const float* bn = bm + (size_t)((j < 2) ? 8 : ((i < 2) ? 48 : 368)) * YPLANE;

                // kd = 0
                if (v0) { mbar_wait(mb0, p0); p0 ^= 1u; }
                if (v2) issue(2, mb2, bm + 2 * YPLANE);
                compute(n, slab);

                // kd = 1
                mbar_wait(mb1, p1); p1 ^= 1u;
                if (!last && v0) issue(0, mb0, bn);
                compute(n + 1, slab + SLOTF);

                // kd = 2
                if (v2) { mbar_wait(mb2, p2); p2 ^= 1u; }
                if (!last) issue(1, mb1, bn + YPLANE);
                compute(n + 2, slab + 2 * SLOTF);

                n += 3;
                bm = bn;
            }
        }
    }

    // ---- epilogue: inverse Winograd + scale + bias
    const float invn = 1.0f / 9.0f;
    const float mb[4] = { mbsh[0], mbsh[1], mbsh[2], mbsh[3] };
    size_t ob = ((((size_t)(b * 4) * 6 + c) * 6 + t) * 8 + d) * (size_t)HW_PLANE;
    const size_t ostride = (size_t)6 * 6 * 8 * HW_PLANE;

    #pragma unroll
    for (int py = 0; py < 3; py++) {
        int h = h0 + 3 * warp + py;
        size_t rowoff = ob + (size_t)h * 96 + 3 * lane;
        float M[4][5];
        #pragma unroll
        for (int cm = 0; cm < 5; cm++) {
            float2 A = unpack2(a01[py][cm]);
            float2 B = unpack2(a23[py][cm]);
            M[0][cm] = A.x; M[1][cm] = A.y; M[2][cm] = B.x; M[3][cm] = B.y;
        }
        #pragma unroll
        for (int o = 0; o < 4; o++) {
            float y0 = M[o][0] + M[o][1] + M[o][2] + M[o][3];
            float y1 = M[o][1] - M[o][2] + 2.f * M[o][3];
            float y2 = M[o][1] + M[o][2] + fmaf(4.f, M[o][3], M[o][4]);
            float* op = out + rowoff + (size_t)o * ostride;
            op[0] = fmaf(y0, invn, mb[o]);
            op[1] = fmaf(y1, invn, mb[o]);
            op[2] = fmaf(y2, invn, mb[o]);
        }
    }
}

extern "C" void kernel_launch(void* const* d_in, const int* in_sizes, int n_in,
                              void* d_out, int out_size) {
    const float* x  = (const float*)d_in[0];
    const float* Wg = (const float*)d_in[1];
    const float* bg = (const float*)d_in[2];
    float* out = (float*)d_out;

    // pass 1: transform all 4096 input planes along w
    xform_kernel<<<4096, 256>>>(x);

    // pass 2: accumulate in Winograd domain
    const int dynsmem = (8 * 3 * SLOTF + 4) * (int)sizeof(float);   // 76816 B
    cudaFuncSetAttribute(conv5d_kernel, cudaFuncAttributeMaxDynamicSharedMemorySize, dynsmem);

    dim3 grid(32, 6, 12);   // x: htile(4) + 4*d(8); y: t(6); z: b*6+c(12)
    dim3 block(256);
    conv5d_kernel<<<grid, block, dynsmem>>>(Wg, bg, out);
}